// round 1
// baseline (speedup 1.0000x reference)
#include <cuda_runtime.h>

#define BB 4096
#define TT 512
#define FF 16
#define HH 256
#define OUT_LEN 64
#define ROWS 16
#define THREADS 256
#define HS 18   // padded row stride (floats)

typedef unsigned long long u64;

// -------- packed weight scratch (static device arrays; no allocation) --------
__device__ float4 g_encW4[HH * HH];   // [k][u] -> (Wi, Wf, Wg, Wo) rows of Whh
__device__ float4 g_decW4[HH * HH];
__device__ float4 g_encX4[FF * HH];   // [f][u]
__device__ float4 g_encB4[HH];
__device__ float4 g_decB4[HH];
__device__ float4 g_decX4[HH];        // dec_Wih is [4H,1]

__global__ void pack_weights(const float* __restrict__ encWih, const float* __restrict__ encWhh,
                             const float* __restrict__ encB,   const float* __restrict__ decWih,
                             const float* __restrict__ decWhh, const float* __restrict__ decB)
{
    int idx = blockIdx.x * blockDim.x + threadIdx.x;
    int k = idx >> 8, u = idx & 255;
    if (idx < HH * HH) {
        g_encW4[idx] = make_float4(encWhh[u * HH + k],          encWhh[(HH + u) * HH + k],
                                   encWhh[(2 * HH + u) * HH + k], encWhh[(3 * HH + u) * HH + k]);
        g_decW4[idx] = make_float4(decWhh[u * HH + k],          decWhh[(HH + u) * HH + k],
                                   decWhh[(2 * HH + u) * HH + k], decWhh[(3 * HH + u) * HH + k]);
    }
    if (idx < FF * HH) { // k == f (0..15)
        g_encX4[idx] = make_float4(encWih[u * FF + k],          encWih[(HH + u) * FF + k],
                                   encWih[(2 * HH + u) * FF + k], encWih[(3 * HH + u) * FF + k]);
    }
    if (idx < HH) {
        g_encB4[idx] = make_float4(encB[idx], encB[HH + idx], encB[2 * HH + idx], encB[3 * HH + idx]);
        g_decB4[idx] = make_float4(decB[idx], decB[HH + idx], decB[2 * HH + idx], decB[3 * HH + idx]);
        g_decX4[idx] = make_float4(decWih[idx], decWih[HH + idx], decWih[2 * HH + idx], decWih[3 * HH + idx]);
    }
}

// -------- packed f32x2 helpers (FFMA2: 2x FMA per issue, fp32 precision) --------
__device__ __forceinline__ u64 pack2(float lo, float hi) {
    u64 r; asm("mov.b64 %0, {%1, %2};" : "=l"(r) : "f"(lo), "f"(hi)); return r;
}
__device__ __forceinline__ void fma2(u64& d, u64 a, u64 b) {
    asm("fma.rn.f32x2 %0, %1, %2, %0;" : "+l"(d) : "l"(a), "l"(b));
}
__device__ __forceinline__ float2 unpack2(u64 v) {
    float2 r; asm("mov.b64 {%0, %1}, %2;" : "=f"(r.x), "=f"(r.y) : "l"(v)); return r;
}
__device__ __forceinline__ float sigf(float x)   { return 1.0f / (1.0f + __expf(-x)); }
__device__ __forceinline__ float tanhf_(float x) { return 2.0f * sigf(2.0f * x) - 1.0f; }

__global__ __launch_bounds__(THREADS, 2)
void lstm_kernel(const float* __restrict__ x, const float* __restrict__ Wout,
                 const float* __restrict__ boutp, float* __restrict__ out)
{
    __shared__ __align__(16) float h_s[HH][HS];
    __shared__ __align__(16) float x_s[FF][HS];
    __shared__ __align__(16) float prev_s[ROWS];
    __shared__ float wout_s[HH];
    __shared__ float bout_s;

    const int u  = threadIdx.x;           // hidden unit owned by this thread
    const int b0 = blockIdx.x * ROWS;     // batch tile base

    wout_s[u] = Wout[u];
    if (u == 0) bout_s = boutp[0];
#pragma unroll
    for (int r = 0; r < ROWS; r++) h_s[u][r] = 0.0f;

    float c[ROWS];
#pragma unroll
    for (int r = 0; r < ROWS; r++) c[r] = 0.0f;

    // ================= encoder: 512 steps =================
    for (int t = 0; t < TT; t++) {
        {   // stage x_t tile: x_s[f][r]
            int f = u >> 4, r = u & 15;
            x_s[f][r] = x[(size_t)(b0 + r) * (TT * FF) + t * FF + f];
        }
        __syncthreads();

        u64 acc[8][4];
        {
            float4 bb = g_encB4[u];
            u64 bi = pack2(bb.x, bb.x), bf = pack2(bb.y, bb.y);
            u64 bg = pack2(bb.z, bb.z), bo = pack2(bb.w, bb.w);
#pragma unroll
            for (int p = 0; p < 8; p++) { acc[p][0] = bi; acc[p][1] = bf; acc[p][2] = bg; acc[p][3] = bo; }
        }

        // x @ Wih^T contribution (K = 16)
#pragma unroll
        for (int f = 0; f < FF; f++) {
            float4 w = g_encX4[f * HH + u];
            u64 wi = pack2(w.x, w.x), wf2 = pack2(w.y, w.y);
            u64 wg = pack2(w.z, w.z), wo  = pack2(w.w, w.w);
            const u64* xp = (const u64*)&x_s[f][0];
#pragma unroll
            for (int p = 0; p < 8; p++) {
                u64 xv = xp[p];
                fma2(acc[p][0], xv, wi); fma2(acc[p][1], xv, wf2);
                fma2(acc[p][2], xv, wg); fma2(acc[p][3], xv, wo);
            }
        }

        // h @ Whh^T contribution (K = 256) — the hot loop
#pragma unroll 2
        for (int k = 0; k < HH; k++) {
            float4 w = g_encW4[k * HH + u];
            u64 wi = pack2(w.x, w.x), wf2 = pack2(w.y, w.y);
            u64 wg = pack2(w.z, w.z), wo  = pack2(w.w, w.w);
            const u64* hp = (const u64*)&h_s[k][0];
#pragma unroll
            for (int p = 0; p < 8; p++) {
                u64 hv = hp[p];
                fma2(acc[p][0], hv, wi); fma2(acc[p][1], hv, wf2);
                fma2(acc[p][2], hv, wg); fma2(acc[p][3], hv, wo);
            }
        }
        __syncthreads();   // all reads of h_s done

        // pointwise gates + state update, write new h
#pragma unroll
        for (int p = 0; p < 8; p++) {
            float2 iv = unpack2(acc[p][0]), fv = unpack2(acc[p][1]);
            float2 gv = unpack2(acc[p][2]), ov = unpack2(acc[p][3]);
            {
                int r = 2 * p;
                c[r] = sigf(fv.x) * c[r] + sigf(iv.x) * tanhf_(gv.x);
                h_s[u][r] = sigf(ov.x) * tanhf_(c[r]);
            }
            {
                int r = 2 * p + 1;
                c[r] = sigf(fv.y) * c[r] + sigf(iv.y) * tanhf_(gv.y);
                h_s[u][r] = sigf(ov.y) * tanhf_(c[r]);
            }
        }
        // next iteration's sync (top of loop) orders these writes before reads
    }
    __syncthreads();
    if (u < ROWS) prev_s[u] = 0.0f;
    __syncthreads();

    // ================= decoder: 64 steps =================
    for (int s = 0; s < OUT_LEN; s++) {
        u64 acc[8][4];
        {
            float4 bb = g_decB4[u];
            u64 bi = pack2(bb.x, bb.x), bf = pack2(bb.y, bb.y);
            u64 bg = pack2(bb.z, bb.z), bo = pack2(bb.w, bb.w);
#pragma unroll
            for (int p = 0; p < 8; p++) { acc[p][0] = bi; acc[p][1] = bf; acc[p][2] = bg; acc[p][3] = bo; }
        }
        {   // scalar input contribution: prev * dec_Wih
            float4 w = g_decX4[u];
            u64 wi = pack2(w.x, w.x), wf2 = pack2(w.y, w.y);
            u64 wg = pack2(w.z, w.z), wo  = pack2(w.w, w.w);
            const u64* pp = (const u64*)prev_s;
#pragma unroll
            for (int p = 0; p < 8; p++) {
                u64 pv = pp[p];
                fma2(acc[p][0], pv, wi); fma2(acc[p][1], pv, wf2);
                fma2(acc[p][2], pv, wg); fma2(acc[p][3], pv, wo);
            }
        }
#pragma unroll 2
        for (int k = 0; k < HH; k++) {
            float4 w = g_decW4[k * HH + u];
            u64 wi = pack2(w.x, w.x), wf2 = pack2(w.y, w.y);
            u64 wg = pack2(w.z, w.z), wo  = pack2(w.w, w.w);
            const u64* hp = (const u64*)&h_s[k][0];
#pragma unroll
            for (int p = 0; p < 8; p++) {
                u64 hv = hp[p];
                fma2(acc[p][0], hv, wi); fma2(acc[p][1], hv, wf2);
                fma2(acc[p][2], hv, wg); fma2(acc[p][3], hv, wo);
            }
        }
        __syncthreads();

#pragma unroll
        for (int p = 0; p < 8; p++) {
            float2 iv = unpack2(acc[p][0]), fv = unpack2(acc[p][1]);
            float2 gv = unpack2(acc[p][2]), ov = unpack2(acc[p][3]);
            {
                int r = 2 * p;
                c[r] = sigf(fv.x) * c[r] + sigf(iv.x) * tanhf_(gv.x);
                h_s[u][r] = sigf(ov.x) * tanhf_(c[r]);
            }
            {
                int r = 2 * p + 1;
                c[r] = sigf(fv.y) * c[r] + sigf(iv.y) * tanhf_(gv.y);
                h_s[u][r] = sigf(ov.y) * tanhf_(c[r]);
            }
        }
        __syncthreads();   // h_s complete before output reduction

        // output head: warp w reduces rows 2w, 2w+1
        {
            int warp = u >> 5, lane = u & 31;
#pragma unroll
            for (int rr = 0; rr < 2; rr++) {
                int r = warp * 2 + rr;
                float p = 0.0f;
#pragma unroll
                for (int i = 0; i < 8; i++) {
                    int kk = lane + 32 * i;
                    p += h_s[kk][r] * wout_s[kk];
                }
#pragma unroll
                for (int off = 16; off; off >>= 1) p += __shfl_xor_sync(0xffffffffu, p, off);
                if (lane == 0) {
                    float val = p + bout_s;
                    out[(size_t)(b0 + r) * OUT_LEN + s] = val;
                    prev_s[r] = val;
                }
            }
        }
        __syncthreads();   // prev_s/h_s stable before next step
    }
}

extern "C" void kernel_launch(void* const* d_in, const int* in_sizes, int n_in,
                              void* d_out, int out_size)
{
    const float* x      = (const float*)d_in[0];
    const float* encWih = (const float*)d_in[1];
    const float* encWhh = (const float*)d_in[2];
    const float* encB   = (const float*)d_in[3];
    const float* decWih = (const float*)d_in[4];
    const float* decWhh = (const float*)d_in[5];
    const float* decB   = (const float*)d_in[6];
    const float* Wout   = (const float*)d_in[7];
    const float* bout   = (const float*)d_in[8];
    float* out = (float*)d_out;

    pack_weights<<<(HH * HH + 255) / 256, 256>>>(encWih, encWhh, encB, decWih, decWhh, decB);
    lstm_kernel<<<BB / ROWS, THREADS>>>(x, Wout, bout, out);
}

// round 2
// speedup vs baseline: 2.2956x; 2.2956x over previous
#include <cuda_runtime.h>

#define BB 4096
#define TT 512
#define FF 16
#define HH 256
#define OUT_LEN 64
#define ROWS 28
#define P2 14            // ROWS/2 packed f32x2 accumulators
#define GRID 147         // ceil(4096/28)
#define THREADS 256
#define HS 30            // padded row stride (floats), even -> 8B aligned

typedef unsigned long long u64;

// -------- packed weight scratch (static device arrays; no allocation) -----
// padded by 2*HH entries so the k+2/k+3 prefetch at the loop tail stays in-bounds
__device__ float4 g_encW4[(HH + 2) * HH];   // [k][u] -> (Wi, Wf, Wg, Wo)
__device__ float4 g_decW4[(HH + 2) * HH];
__device__ float4 g_encX4[FF * HH];         // [f][u]
__device__ float4 g_encB4[HH];
__device__ float4 g_decB4[HH];
__device__ float4 g_decX4[HH];              // dec_Wih is [4H,1]

__global__ void pack_weights(const float* __restrict__ encWih, const float* __restrict__ encWhh,
                             const float* __restrict__ encB,   const float* __restrict__ decWih,
                             const float* __restrict__ decWhh, const float* __restrict__ decB)
{
    int idx = blockIdx.x * blockDim.x + threadIdx.x;
    int k = idx >> 8, u = idx & 255;
    if (idx < HH * HH) {
        g_encW4[idx] = make_float4(encWhh[u * HH + k],            encWhh[(HH + u) * HH + k],
                                   encWhh[(2 * HH + u) * HH + k], encWhh[(3 * HH + u) * HH + k]);
        g_decW4[idx] = make_float4(decWhh[u * HH + k],            decWhh[(HH + u) * HH + k],
                                   decWhh[(2 * HH + u) * HH + k], decWhh[(3 * HH + u) * HH + k]);
    }
    if (idx < FF * HH) { // k == f (0..15)
        g_encX4[idx] = make_float4(encWih[u * FF + k],            encWih[(HH + u) * FF + k],
                                   encWih[(2 * HH + u) * FF + k], encWih[(3 * HH + u) * FF + k]);
    }
    if (idx < HH) {
        g_encB4[idx] = make_float4(encB[idx], encB[HH + idx], encB[2 * HH + idx], encB[3 * HH + idx]);
        g_decB4[idx] = make_float4(decB[idx], decB[HH + idx], decB[2 * HH + idx], decB[3 * HH + idx]);
        g_decX4[idx] = make_float4(decWih[idx], decWih[HH + idx], decWih[2 * HH + idx], decWih[3 * HH + idx]);
    }
}

// -------- packed f32x2 helpers --------
__device__ __forceinline__ u64 pack2(float lo, float hi) {
    u64 r; asm("mov.b64 %0, {%1, %2};" : "=l"(r) : "f"(lo), "f"(hi)); return r;
}
__device__ __forceinline__ void fma2(u64& d, u64 a, u64 b) {
    asm("fma.rn.f32x2 %0, %1, %2, %0;" : "+l"(d) : "l"(a), "l"(b));
}
__device__ __forceinline__ float2 unpack2(u64 v) {
    float2 r; asm("mov.b64 {%0, %1}, %2;" : "=f"(r.x), "=f"(r.y) : "l"(v)); return r;
}
__device__ __forceinline__ float tanh_fast(float x) {
    float r; asm("tanh.approx.f32 %0, %1;" : "=f"(r) : "f"(x)); return r;
}
__device__ __forceinline__ float sig_fast(float x) {
    return fmaf(0.5f, tanh_fast(0.5f * x), 0.5f);
}

// One 2-k step of the gate GEMM with register prefetch already done by caller.
#define GATE_K2(wa, wb, hp, hq)                                                  \
    {                                                                            \
        u64 ai = pack2(wa.x, wa.x), af = pack2(wa.y, wa.y);                      \
        u64 ag = pack2(wa.z, wa.z), ao = pack2(wa.w, wa.w);                      \
        _Pragma("unroll")                                                        \
        for (int p = 0; p < P2; p++) {                                           \
            u64 hv = hp[p];                                                      \
            fma2(acc[p][0], hv, ai); fma2(acc[p][1], hv, af);                    \
            fma2(acc[p][2], hv, ag); fma2(acc[p][3], hv, ao);                    \
        }                                                                        \
        u64 bi = pack2(wb.x, wb.x), bf = pack2(wb.y, wb.y);                      \
        u64 bg = pack2(wb.z, wb.z), bo = pack2(wb.w, wb.w);                      \
        _Pragma("unroll")                                                        \
        for (int p = 0; p < P2; p++) {                                           \
            u64 hv = hq[p];                                                      \
            fma2(acc[p][0], hv, bi); fma2(acc[p][1], hv, bf);                    \
            fma2(acc[p][2], hv, bg); fma2(acc[p][3], hv, bo);                    \
        }                                                                        \
    }

__global__ __launch_bounds__(THREADS, 1)
void lstm_kernel(const float* __restrict__ x, const float* __restrict__ Wout,
                 const float* __restrict__ boutp, float* __restrict__ out)
{
    __shared__ __align__(16) float h_s[HH][HS];
    __shared__ __align__(16) float x_s[FF][HS];
    __shared__ __align__(16) float prev_s[ROWS];
    __shared__ float wout_s[HH];
    __shared__ float bout_s;

    const int u  = threadIdx.x;           // hidden unit owned by this thread
    const int b0 = blockIdx.x * ROWS;     // batch tile base

    wout_s[u] = Wout[u];
    if (u == 0) bout_s = boutp[0];
#pragma unroll
    for (int r = 0; r < ROWS; r++) h_s[u][r] = 0.0f;

    float c[ROWS];
#pragma unroll
    for (int r = 0; r < ROWS; r++) c[r] = 0.0f;

    // ================= encoder: 512 steps =================
    for (int t = 0; t < TT; t++) {
        {   // stage x_t tile: x_s[f][r]  (coalesced: 16 consecutive f per 16-thread group)
            int idx = u;
#pragma unroll
            for (int it = 0; it < 2; it++, idx += THREADS) {
                if (idx < FF * ROWS) {
                    int r = idx >> 4, f = idx & 15;
                    int b = b0 + r; if (b >= BB) b = BB - 1;   // clamp for partial last tile
                    x_s[f][r] = x[(size_t)b * (TT * FF) + t * FF + f];
                }
            }
        }
        __syncthreads();

        u64 acc[P2][4];
        {
            float4 bb = g_encB4[u];
            u64 bi = pack2(bb.x, bb.x), bf = pack2(bb.y, bb.y);
            u64 bg = pack2(bb.z, bb.z), bo = pack2(bb.w, bb.w);
#pragma unroll
            for (int p = 0; p < P2; p++) { acc[p][0] = bi; acc[p][1] = bf; acc[p][2] = bg; acc[p][3] = bo; }
        }

        // x @ Wih^T contribution (K = 16, fully unrolled -> MLP covers latency)
#pragma unroll
        for (int f = 0; f < FF; f += 2) {
            float4 wa = g_encX4[f * HH + u];
            float4 wb = g_encX4[(f + 1) * HH + u];
            const u64* hp = (const u64*)&x_s[f][0];
            const u64* hq = (const u64*)&x_s[f + 1][0];
            GATE_K2(wa, wb, hp, hq);
        }

        // h @ Whh^T contribution (K = 256) — hot loop with 1-iter-ahead prefetch
        {
            float4 wA = g_encW4[u];
            float4 wB = g_encW4[HH + u];
            for (int k = 0; k < HH; k += 2) {
                float4 wa = wA, wb = wB;
                wA = g_encW4[(k + 2) * HH + u];   // padded: always in-bounds
                wB = g_encW4[(k + 3) * HH + u];
                const u64* hp = (const u64*)&h_s[k][0];
                const u64* hq = (const u64*)&h_s[k + 1][0];
                GATE_K2(wa, wb, hp, hq);
            }
        }
        __syncthreads();   // all reads of h_s / x_s done

        // pointwise gates + state update, write new h
#pragma unroll
        for (int p = 0; p < P2; p++) {
            float2 iv = unpack2(acc[p][0]), fv = unpack2(acc[p][1]);
            float2 gv = unpack2(acc[p][2]), ov = unpack2(acc[p][3]);
            {
                int r = 2 * p;
                c[r] = sig_fast(fv.x) * c[r] + sig_fast(iv.x) * tanh_fast(gv.x);
                h_s[u][r] = sig_fast(ov.x) * tanh_fast(c[r]);
            }
            {
                int r = 2 * p + 1;
                c[r] = sig_fast(fv.y) * c[r] + sig_fast(iv.y) * tanh_fast(gv.y);
                h_s[u][r] = sig_fast(ov.y) * tanh_fast(c[r]);
            }
        }
        // next iteration's barrier (after x staging) orders these writes before reads
    }
    __syncthreads();
    if (u < ROWS) prev_s[u] = 0.0f;
    __syncthreads();

    // ================= decoder: 64 steps =================
    for (int s = 0; s < OUT_LEN; s++) {
        u64 acc[P2][4];
        {
            float4 bb = g_decB4[u];
            u64 bi = pack2(bb.x, bb.x), bf = pack2(bb.y, bb.y);
            u64 bg = pack2(bb.z, bb.z), bo = pack2(bb.w, bb.w);
#pragma unroll
            for (int p = 0; p < P2; p++) { acc[p][0] = bi; acc[p][1] = bf; acc[p][2] = bg; acc[p][3] = bo; }
        }
        {   // scalar input contribution: prev * dec_Wih
            float4 w = g_decX4[u];
            u64 wi = pack2(w.x, w.x), wf2 = pack2(w.y, w.y);
            u64 wg = pack2(w.z, w.z), wo  = pack2(w.w, w.w);
            const u64* pp = (const u64*)prev_s;
#pragma unroll
            for (int p = 0; p < P2; p++) {
                u64 pv = pp[p];
                fma2(acc[p][0], pv, wi); fma2(acc[p][1], pv, wf2);
                fma2(acc[p][2], pv, wg); fma2(acc[p][3], pv, wo);
            }
        }
        {
            float4 wA = g_decW4[u];
            float4 wB = g_decW4[HH + u];
            for (int k = 0; k < HH; k += 2) {
                float4 wa = wA, wb = wB;
                wA = g_decW4[(k + 2) * HH + u];
                wB = g_decW4[(k + 3) * HH + u];
                const u64* hp = (const u64*)&h_s[k][0];
                const u64* hq = (const u64*)&h_s[k + 1][0];
                GATE_K2(wa, wb, hp, hq);
            }
        }
        __syncthreads();

#pragma unroll
        for (int p = 0; p < P2; p++) {
            float2 iv = unpack2(acc[p][0]), fv = unpack2(acc[p][1]);
            float2 gv = unpack2(acc[p][2]), ov = unpack2(acc[p][3]);
            {
                int r = 2 * p;
                c[r] = sig_fast(fv.x) * c[r] + sig_fast(iv.x) * tanh_fast(gv.x);
                h_s[u][r] = sig_fast(ov.x) * tanh_fast(c[r]);
            }
            {
                int r = 2 * p + 1;
                c[r] = sig_fast(fv.y) * c[r] + sig_fast(iv.y) * tanh_fast(gv.y);
                h_s[u][r] = sig_fast(ov.y) * tanh_fast(c[r]);
            }
        }
        __syncthreads();   // h_s complete before output reduction

        // output head: warp w reduces rows w, w+8, w+16, w+24
        {
            int warp = u >> 5, lane = u & 31;
#pragma unroll
            for (int j = 0; j < 4; j++) {
                int r = warp + 8 * j;
                if (r < ROWS) {
                    float p = 0.0f;
#pragma unroll
                    for (int i = 0; i < 8; i++) {
                        int kk = lane + 32 * i;
                        p += h_s[kk][r] * wout_s[kk];
                    }
#pragma unroll
                    for (int off = 16; off; off >>= 1) p += __shfl_xor_sync(0xffffffffu, p, off);
                    if (lane == 0) {
                        float val = p + bout_s;
                        if (b0 + r < BB) out[(size_t)(b0 + r) * OUT_LEN + s] = val;
                        prev_s[r] = val;
                    }
                }
            }
        }
        __syncthreads();   // prev_s/h_s stable before next step
    }
}

extern "C" void kernel_launch(void* const* d_in, const int* in_sizes, int n_in,
                              void* d_out, int out_size)
{
    const float* x      = (const float*)d_in[0];
    const float* encWih = (const float*)d_in[1];
    const float* encWhh = (const float*)d_in[2];
    const float* encB   = (const float*)d_in[3];
    const float* decWih = (const float*)d_in[4];
    const float* decWhh = (const float*)d_in[5];
    const float* decB   = (const float*)d_in[6];
    const float* Wout   = (const float*)d_in[7];
    const float* bout   = (const float*)d_in[8];
    float* out = (float*)d_out;

    pack_weights<<<(HH * HH + 255) / 256, 256>>>(encWih, encWhh, encB, decWih, decWhh, decB);
    lstm_kernel<<<GRID, THREADS>>>(x, Wout, bout, out);
}